// round 2
// baseline (speedup 1.0000x reference)
#include <cuda_runtime.h>
#include <math.h>

#define BATCH   2
#define SEQ     2048
#define DIM     1024
#define NHEADS  16
#define DH      64
#define NTOK    (BATCH*SEQ)          // 4096
#define QKVC    (3*NHEADS*DH)        // 3072

typedef unsigned long long ull;

// ---------- packed f32x2 helpers (Blackwell FFMA2 path) ----------
__device__ __forceinline__ ull dup2f(float x) {
    ull r; asm("mov.b64 %0, {%1, %1};" : "=l"(r) : "f"(x)); return r;
}
__device__ __forceinline__ void ffma2(ull& d, ull a, ull b) {
    asm("fma.rn.f32x2 %0, %1, %2, %0;" : "+l"(d) : "l"(a), "l"(b));
}
__device__ __forceinline__ ull fmul2(ull a, ull b) {
    ull d; asm("mul.rn.f32x2 %0, %1, %2;" : "=l"(d) : "l"(a), "l"(b)); return d;
}
__device__ __forceinline__ float2 unpk(ull v) {
    float2 r; asm("mov.b64 {%0, %1}, %2;" : "=f"(r.x), "=f"(r.y) : "l"(v)); return r;
}

// -------- scratch (allocation-free: __device__ globals) --------
__device__ float g_xn [(size_t)NTOK * DIM];    // 16 MB
__device__ float g_qkv[(size_t)NTOK * QKVC];   // 48 MB
__device__ float g_gate[NTOK * NHEADS];        // 256 KB
__device__ float g_att[(size_t)NTOK * DIM];    // 16 MB

// ============================================================
// 1) RMSNorm variant: xn = x / ||x||_2 * gamma * sqrt(DIM)
// ============================================================
__global__ __launch_bounds__(256) void rmsnorm_k(const float* __restrict__ x,
                                                 const float* __restrict__ gamma)
{
    int t = blockIdx.x;
    const float4* xr = (const float4*)(x + (size_t)t * DIM);
    float4 a = xr[threadIdx.x];
    float ss = a.x*a.x + a.y*a.y + a.z*a.z + a.w*a.w;

    __shared__ float red[8];
    #pragma unroll
    for (int o = 16; o; o >>= 1) ss += __shfl_xor_sync(0xFFFFFFFFu, ss, o);
    if ((threadIdx.x & 31) == 0) red[threadIdx.x >> 5] = ss;
    __syncthreads();
    if (threadIdx.x < 32) {
        float s2 = (threadIdx.x < 8) ? red[threadIdx.x] : 0.0f;
        #pragma unroll
        for (int o = 4; o; o >>= 1) s2 += __shfl_xor_sync(0xFFFFFFFFu, s2, o);
        if (threadIdx.x == 0) red[0] = s2;
    }
    __syncthreads();
    float inv = rsqrtf(red[0]) * 32.0f;  // sqrt(1024) = 32
    const float4* g4 = (const float4*)gamma;
    float4 g = g4[threadIdx.x];
    float4 o4 = make_float4(a.x*inv*g.x, a.y*inv*g.y, a.z*inv*g.z, a.w*inv*g.w);
    ((float4*)(g_xn + (size_t)t * DIM))[threadIdx.x] = o4;
}

// ============================================================
// 2) SGEMM f32x2: C[M,N] = A[M,K] @ B[K,N].
//    128x128 tile, BK=8, 256 thr, 8x8/thread as 8x4 packed pairs.
//    A stored duplicated (ull) in smem so inner loop has no packing.
// ============================================================
__global__ __launch_bounds__(256) void sgemm_k(const float* __restrict__ A,
                                               const float* __restrict__ Bm,
                                               float* __restrict__ C,
                                               int M, int Nn, int K)
{
    __shared__ ull   As2[8][128];   // duplicated pairs (a,a)
    __shared__ float Bs [8][128];

    int tid = threadIdx.x;
    int tx = tid & 15, ty = tid >> 4;

    int aRow = tid >> 1;
    int aCol = (tid & 1) * 4;
    int bRow = tid >> 5;
    int bCol = (tid & 31) * 4;

    const float* Ap = A + (size_t)(blockIdx.y * 128 + aRow) * K + aCol;
    const float* Bp = Bm + (size_t)bRow * Nn + blockIdx.x * 128 + bCol;

    ull acc[8][4];
    #pragma unroll
    for (int i = 0; i < 8; i++)
        #pragma unroll
        for (int j = 0; j < 4; j++) acc[i][j] = 0ull;

    for (int kt = 0; kt < K; kt += 8) {
        float4 a = *(const float4*)Ap;  Ap += 8;
        float4 b = *(const float4*)Bp;  Bp += (size_t)8 * Nn;

        __syncthreads();
        As2[aCol+0][aRow] = dup2f(a.x);
        As2[aCol+1][aRow] = dup2f(a.y);
        As2[aCol+2][aRow] = dup2f(a.z);
        As2[aCol+3][aRow] = dup2f(a.w);
        *(float4*)&Bs[bRow][bCol] = b;
        __syncthreads();

        #pragma unroll
        for (int k = 0; k < 8; k++) {
            ulonglong2 a01 = *(const ulonglong2*)&As2[k][ty*4];
            ulonglong2 a23 = *(const ulonglong2*)&As2[k][ty*4 + 2];
            ulonglong2 a45 = *(const ulonglong2*)&As2[k][64 + ty*4];
            ulonglong2 a67 = *(const ulonglong2*)&As2[k][64 + ty*4 + 2];
            ulonglong2 b01 = *(const ulonglong2*)&Bs[k][tx*4];        // cols j..j+3
            ulonglong2 b23 = *(const ulonglong2*)&Bs[k][64 + tx*4];
            ull ar[8] = {a01.x, a01.y, a23.x, a23.y, a45.x, a45.y, a67.x, a67.y};
            #pragma unroll
            for (int i = 0; i < 8; i++) {
                ffma2(acc[i][0], ar[i], b01.x);
                ffma2(acc[i][1], ar[i], b01.y);
                ffma2(acc[i][2], ar[i], b23.x);
                ffma2(acc[i][3], ar[i], b23.y);
            }
        }
    }

    int m0 = blockIdx.y * 128, n0 = blockIdx.x * 128;
    #pragma unroll
    for (int i = 0; i < 8; i++) {
        int row = m0 + ((i < 4) ? (ty*4 + i) : (64 + ty*4 + i - 4));
        float* cp = C + (size_t)row * Nn + n0;
        float2 u0 = unpk(acc[i][0]), u1 = unpk(acc[i][1]);
        float2 u2 = unpk(acc[i][2]), u3 = unpk(acc[i][3]);
        *(float4*)(cp + tx*4)      = make_float4(u0.x, u0.y, u1.x, u1.y);
        *(float4*)(cp + 64 + tx*4) = make_float4(u2.x, u2.y, u3.x, u3.y);
    }
}

// ============================================================
// 3) Gates: gate[t,h] = sigmoid(xn[t,:] @ w_gates[:,h] + b[h])
// ============================================================
__global__ __launch_bounds__(256) void gates_k(const float* __restrict__ wg,
                                               const float* __restrict__ bg)
{
    int t = blockIdx.x;
    int tid = threadIdx.x;
    int h = tid & 15, chunk = tid >> 4;
    const float* xr = g_xn + (size_t)t * DIM;
    float acc = 0.0f;
    int d0 = chunk * 64;
    #pragma unroll 8
    for (int d = d0; d < d0 + 64; d++) acc += xr[d] * wg[d * NHEADS + h];

    __shared__ float s[16][16];
    s[chunk][h] = acc;
    __syncthreads();
    if (tid < 16) {
        float v = bg[tid];
        #pragma unroll
        for (int c = 0; c < 16; c++) v += s[c][tid];
        g_gate[t * NHEADS + tid] = 1.0f / (1.0f + expf(-v));
    }
}

// ============================================================
// 4) RoPE (interleaved) in-place on q and k planes
// ============================================================
__global__ __launch_bounds__(256) void rope_k(const float* __restrict__ freqs)
{
    int t = blockIdx.x;
    int pos = t & (SEQ - 1);
    for (int p = threadIdx.x; p < 1024; p += 256) {
        int mat = p >> 9;
        int rem = p & 511;
        int h = rem >> 5;
        int i = rem & 31;
        float f = (float)pos * freqs[i];
        float sn, cs;
        sincosf(f, &sn, &cs);
        float2* ptr = (float2*)(g_qkv + (size_t)t * QKVC + mat * 1024 + h * DH + 2 * i);
        float2 v = *ptr;
        *ptr = make_float2(v.x * cs - v.y * sn, v.y * cs + v.x * sn);
    }
}

// ============================================================
// 5) Flash attention, packed f32x2 + gate in epilogue.
//    grid (SEQ/64, NHEADS, BATCH), 256 thr = 8 warps.
//    Warp owns 8 q rows. Lane owns keys {2l, 2l+1} (one LDS64 from
//    transposed K) and output dims {2l, 2l+1}.
//    Smem: Qdup (ull) 32K | Kt (f32, pad66) 16.5K | V 16K | Pdup (ull) 32K
// ============================================================
#define ATTN_SMEM_BYTES (64*64*8 + 64*66*4 + 64*64*4 + 8*8*64*8)
__global__ __launch_bounds__(256) void attn_k()
{
    extern __shared__ char smraw[];
    ull*   Qd = (ull*)smraw;                         // [64][64] dup pairs
    float* Kt = (float*)(smraw + 64*64*8);           // [64 d][66] transposed
    float* Vs = (float*)(smraw + 64*64*8 + 64*66*4); // [64][64]
    ull*   P2 = (ull*)(smraw + 64*64*8 + 64*66*4 + 64*64*4); // [8 warps][8r][64k] dup

    int qt = blockIdx.x, h = blockIdx.y, b = blockIdx.z;
    int tid = threadIdx.x, warp = tid >> 5, lane = tid & 31;
    int tBase = b * SEQ + qt * 64;
    int kl = lane * 2;
    const float scale = 0.125f;

    // load Q tile, pre-scaled + duplicated
    for (int idx = tid; idx < 64 * 16; idx += 256) {
        int r = idx >> 4, c4 = (idx & 15) << 2;
        float4 v = *(const float4*)(g_qkv + (size_t)(tBase + r) * QKVC + h * DH + c4);
        ull* qd = &Qd[r * 64 + c4];
        qd[0] = dup2f(v.x * scale); qd[1] = dup2f(v.y * scale);
        qd[2] = dup2f(v.z * scale); qd[3] = dup2f(v.w * scale);
    }

    float m[8], l[8];
    ull o2[8];
    #pragma unroll
    for (int r = 0; r < 8; r++) { m[r] = -INFINITY; l[r] = 0.0f; o2[r] = 0ull; }

    int r0 = warp * 8;
    ull* Pw = P2 + warp * 512;

    for (int kt = 0; kt < SEQ / 64; kt++) {
        __syncthreads();
        int kBase = b * SEQ + kt * 64;
        for (int idx = tid; idx < 64 * 16; idx += 256) {
            int r = idx >> 4, c4 = (idx & 15) << 2;   // r = key, c4 = dims
            float4 kv = *(const float4*)(g_qkv + (size_t)(kBase + r) * QKVC + 1024 + h * DH + c4);
            Kt[(c4+0)*66 + r] = kv.x; Kt[(c4+1)*66 + r] = kv.y;
            Kt[(c4+2)*66 + r] = kv.z; Kt[(c4+3)*66 + r] = kv.w;
            float4 vv = *(const float4*)(g_qkv + (size_t)(kBase + r) * QKVC + 2048 + h * DH + c4);
            *(float4*)&Vs[r * 64 + c4] = vv;
        }
        __syncthreads();

        // S = Q K^T : packed over key pair (2l, 2l+1)
        ull s2[8];
        #pragma unroll
        for (int r = 0; r < 8; r++) s2[r] = 0ull;
        #pragma unroll 4
        for (int d4 = 0; d4 < 64; d4 += 4) {
            ull kp0 = *(const ull*)&Kt[(d4+0)*66 + kl];
            ull kp1 = *(const ull*)&Kt[(d4+1)*66 + kl];
            ull kp2 = *(const ull*)&Kt[(d4+2)*66 + kl];
            ull kp3 = *(const ull*)&Kt[(d4+3)*66 + kl];
            #pragma unroll
            for (int r = 0; r < 8; r++) {
                const ulonglong2* q = (const ulonglong2*)&Qd[(r0 + r) * 64 + d4];
                ulonglong2 qa = q[0], qb = q[1];
                ffma2(s2[r], qa.x, kp0);
                ffma2(s2[r], qa.y, kp1);
                ffma2(s2[r], qb.x, kp2);
                ffma2(s2[r], qb.y, kp3);
            }
        }

        // online softmax; write duplicated P to warp-private smem
        #pragma unroll
        for (int r = 0; r < 8; r++) {
            float2 s = unpk(s2[r]);
            float mx = fmaxf(s.x, s.y);
            #pragma unroll
            for (int o = 16; o; o >>= 1) mx = fmaxf(mx, __shfl_xor_sync(0xFFFFFFFFu, mx, o));
            float mn = fmaxf(m[r], mx);
            float corr = __expf(m[r] - mn);
            float p0 = __expf(s.x - mn);
            float p1 = __expf(s.y - mn);
            float rs = p0 + p1;
            #pragma unroll
            for (int o = 16; o; o >>= 1) rs += __shfl_xor_sync(0xFFFFFFFFu, rs, o);
            l[r] = l[r] * corr + rs;
            m[r] = mn;
            o2[r] = fmul2(o2[r], dup2f(corr));
            ulonglong2 pp; pp.x = dup2f(p0); pp.y = dup2f(p1);
            *(ulonglong2*)&Pw[r * 64 + kl] = pp;
        }
        __syncwarp();

        // O += P V : packed over dim pair (2l, 2l+1)
        #pragma unroll 4
        for (int kk = 0; kk < 64; kk += 4) {
            ull v0 = *(const ull*)&Vs[(kk+0)*64 + kl];
            ull v1 = *(const ull*)&Vs[(kk+1)*64 + kl];
            ull v2 = *(const ull*)&Vs[(kk+2)*64 + kl];
            ull v3 = *(const ull*)&Vs[(kk+3)*64 + kl];
            #pragma unroll
            for (int r = 0; r < 8; r++) {
                const ulonglong2* p = (const ulonglong2*)&Pw[r * 64 + kk];
                ulonglong2 pa = p[0], pb = p[1];
                ffma2(o2[r], pa.x, v0);
                ffma2(o2[r], pa.y, v1);
                ffma2(o2[r], pb.x, v2);
                ffma2(o2[r], pb.y, v3);
            }
        }
    }

    // epilogue: normalize, gate, store merged-head layout
    #pragma unroll
    for (int r = 0; r < 8; r++) {
        int t = tBase + r0 + r;
        float sc = (1.0f / l[r]) * g_gate[t * NHEADS + h];
        float2 u = unpk(o2[r]);
        *(float2*)(g_att + (size_t)t * DIM + h * DH + kl) =
            make_float2(u.x * sc, u.y * sc);
    }
}

// ============================================================
// launcher
// ============================================================
extern "C" void kernel_launch(void* const* d_in, const int* in_sizes, int n_in,
                              void* d_out, int out_size)
{
    const float* x       = (const float*)d_in[0];
    const float* gamma   = (const float*)d_in[1];
    const float* w_qkv   = (const float*)d_in[2];
    const float* w_gates = (const float*)d_in[3];
    const float* b_gates = (const float*)d_in[4];
    const float* w_out   = (const float*)d_in[5];
    const float* freqs   = (const float*)d_in[6];
    float* out = (float*)d_out;

    float *xn_p, *qkv_p, *att_p;
    cudaGetSymbolAddress((void**)&xn_p,  g_xn);
    cudaGetSymbolAddress((void**)&qkv_p, g_qkv);
    cudaGetSymbolAddress((void**)&att_p, g_att);

    cudaFuncSetAttribute(attn_k, cudaFuncAttributeMaxDynamicSharedMemorySize,
                         ATTN_SMEM_BYTES);

    rmsnorm_k<<<NTOK, 256>>>(x, gamma);
    sgemm_k<<<dim3(QKVC / 128, NTOK / 128), 256>>>(xn_p, w_qkv, qkv_p, NTOK, QKVC, DIM);
    gates_k<<<NTOK, 256>>>(w_gates, b_gates);
    rope_k<<<NTOK, 256>>>(freqs);
    attn_k<<<dim3(SEQ / 64, NHEADS, BATCH), 256, ATTN_SMEM_BYTES>>>();
    sgemm_k<<<dim3(DIM / 128, NTOK / 128), 256>>>(att_p, w_out, out, NTOK, DIM, DIM);
}

// round 3
// speedup vs baseline: 3.6172x; 3.6172x over previous
#include <cuda_runtime.h>
#include <math.h>

#define BATCH   2
#define SEQ     2048
#define DIM     1024
#define NHEADS  16
#define DH      64
#define NTOK    (BATCH*SEQ)          // 4096
#define QKVC    (3*NHEADS*DH)        // 3072

// -------- scratch (allocation-free: __device__ globals) --------
__device__ float g_xn [(size_t)NTOK * DIM];    // 16 MB
__device__ float g_qkv[(size_t)NTOK * QKVC];   // 48 MB
__device__ float g_gate[NTOK * NHEADS];        // 256 KB
__device__ float g_att[(size_t)NTOK * DIM];    // 16 MB

// ---------- tf32 helpers ----------
__device__ __forceinline__ float tf32r(float x) {
    unsigned u; asm("cvt.rna.tf32.f32 %0, %1;" : "=r"(u) : "f"(x));
    return __uint_as_float(u);
}
__device__ __forceinline__ void mma_tf32(float* d, const unsigned* a,
                                         unsigned b0, unsigned b1) {
    asm volatile("mma.sync.aligned.m16n8k8.row.col.f32.tf32.tf32.f32 "
        "{%0,%1,%2,%3}, {%4,%5,%6,%7}, {%8,%9}, {%0,%1,%2,%3};"
        : "+f"(d[0]), "+f"(d[1]), "+f"(d[2]), "+f"(d[3])
        : "r"(a[0]), "r"(a[1]), "r"(a[2]), "r"(a[3]), "r"(b0), "r"(b1));
}
__device__ __forceinline__ unsigned f2u(float x) { return __float_as_uint(x); }

// ============================================================
// 1) RMSNorm variant: xn = x / ||x||_2 * gamma * sqrt(DIM)
// ============================================================
__global__ __launch_bounds__(256) void rmsnorm_k(const float* __restrict__ x,
                                                 const float* __restrict__ gamma)
{
    int t = blockIdx.x;
    const float4* xr = (const float4*)(x + (size_t)t * DIM);
    float4 a = xr[threadIdx.x];
    float ss = a.x*a.x + a.y*a.y + a.z*a.z + a.w*a.w;

    __shared__ float red[8];
    #pragma unroll
    for (int o = 16; o; o >>= 1) ss += __shfl_xor_sync(0xFFFFFFFFu, ss, o);
    if ((threadIdx.x & 31) == 0) red[threadIdx.x >> 5] = ss;
    __syncthreads();
    if (threadIdx.x < 32) {
        float s2 = (threadIdx.x < 8) ? red[threadIdx.x] : 0.0f;
        #pragma unroll
        for (int o = 4; o; o >>= 1) s2 += __shfl_xor_sync(0xFFFFFFFFu, s2, o);
        if (threadIdx.x == 0) red[0] = s2;
    }
    __syncthreads();
    float inv = rsqrtf(red[0]) * 32.0f;
    const float4* g4 = (const float4*)gamma;
    float4 g = g4[threadIdx.x];
    float4 o4 = make_float4(a.x*inv*g.x, a.y*inv*g.y, a.z*inv*g.z, a.w*inv*g.w);
    ((float4*)(g_xn + (size_t)t * DIM))[threadIdx.x] = o4;
}

// ============================================================
// 2) TF32 tensor-core GEMM: C[M,N] = A[M,K] @ B[K,N] row-major.
//    BM=128 BN=128 BK=16, 256 thr = 8 warps (2m x 4n), warp 64x32.
// ============================================================
__global__ __launch_bounds__(256) void tgemm_k(const float* __restrict__ A,
                                               const float* __restrict__ Bm,
                                               float* __restrict__ C,
                                               int M, int Nn, int K)
{
    __shared__ float As[128][20];    // [m][k], pad 20 (20g+tig distinct banks)
    __shared__ float Bs[16][136];    // [k][n], pad 136 (8tig+g distinct banks)

    int tid = threadIdx.x;
    int warp = tid >> 5, lane = tid & 31;
    int g = lane >> 2, tig = lane & 3;
    int wm = (warp >> 2) * 64;
    int wn = (warp & 3) * 32;

    int ar = tid >> 2;               // 0..63
    int ac = (tid & 3) * 4;
    int br = tid >> 4;               // 0..15
    int bc = (tid & 15) * 8;

    const float* Ap = A + (size_t)(blockIdx.y * 128) * K + ac;
    const float* Bp = Bm + (size_t)br * Nn + blockIdx.x * 128 + bc;

    float acc[4][4][4];
    #pragma unroll
    for (int i = 0; i < 4; i++)
        #pragma unroll
        for (int j = 0; j < 4; j++)
            #pragma unroll
            for (int r = 0; r < 4; r++) acc[i][j][r] = 0.0f;

    for (int kt = 0; kt < K; kt += 16) {
        float4 la0 = *(const float4*)(Ap + (size_t)ar * K);
        float4 la1 = *(const float4*)(Ap + (size_t)(ar + 64) * K);
        float4 lb0 = *(const float4*)Bp;
        float4 lb1 = *(const float4*)(Bp + 4);
        Ap += 16; Bp += (size_t)16 * Nn;

        __syncthreads();
        *(float4*)&As[ar][ac] = make_float4(tf32r(la0.x), tf32r(la0.y), tf32r(la0.z), tf32r(la0.w));
        *(float4*)&As[ar+64][ac] = make_float4(tf32r(la1.x), tf32r(la1.y), tf32r(la1.z), tf32r(la1.w));
        *(float4*)&Bs[br][bc]   = make_float4(tf32r(lb0.x), tf32r(lb0.y), tf32r(lb0.z), tf32r(lb0.w));
        *(float4*)&Bs[br][bc+4] = make_float4(tf32r(lb1.x), tf32r(lb1.y), tf32r(lb1.z), tf32r(lb1.w));
        __syncthreads();

        #pragma unroll
        for (int ks = 0; ks < 2; ks++) {
            int k0 = ks * 8;
            unsigned af[4][4], bf[4][2];
            #pragma unroll
            for (int mt = 0; mt < 4; mt++) {
                int rb = wm + mt * 16 + g;
                af[mt][0] = f2u(As[rb    ][k0 + tig]);
                af[mt][1] = f2u(As[rb + 8][k0 + tig]);
                af[mt][2] = f2u(As[rb    ][k0 + tig + 4]);
                af[mt][3] = f2u(As[rb + 8][k0 + tig + 4]);
            }
            #pragma unroll
            for (int nt = 0; nt < 4; nt++) {
                int cb = wn + nt * 8 + g;
                bf[nt][0] = f2u(Bs[k0 + tig    ][cb]);
                bf[nt][1] = f2u(Bs[k0 + tig + 4][cb]);
            }
            #pragma unroll
            for (int mt = 0; mt < 4; mt++)
                #pragma unroll
                for (int nt = 0; nt < 4; nt++)
                    mma_tf32(acc[mt][nt], af[mt], bf[nt][0], bf[nt][1]);
        }
    }

    int m0 = blockIdx.y * 128 + wm, n0 = blockIdx.x * 128 + wn;
    #pragma unroll
    for (int mt = 0; mt < 4; mt++) {
        int row = m0 + mt * 16 + g;
        #pragma unroll
        for (int nt = 0; nt < 4; nt++) {
            int col = n0 + nt * 8 + 2 * tig;
            *(float2*)&C[(size_t)row * Nn + col]       = make_float2(acc[mt][nt][0], acc[mt][nt][1]);
            *(float2*)&C[(size_t)(row + 8) * Nn + col] = make_float2(acc[mt][nt][2], acc[mt][nt][3]);
        }
    }
}

// ============================================================
// 3) Gates: gate[t,h] = sigmoid(xn[t,:] @ w_gates[:,h] + b[h])
// ============================================================
__global__ __launch_bounds__(256) void gates_k(const float* __restrict__ wg,
                                               const float* __restrict__ bg)
{
    int t = blockIdx.x;
    int tid = threadIdx.x;
    int h = tid & 15, chunk = tid >> 4;
    const float* xr = g_xn + (size_t)t * DIM;
    float acc = 0.0f;
    int d0 = chunk * 64;
    #pragma unroll 8
    for (int d = d0; d < d0 + 64; d++) acc += xr[d] * wg[d * NHEADS + h];

    __shared__ float s[16][16];
    s[chunk][h] = acc;
    __syncthreads();
    if (tid < 16) {
        float v = bg[tid];
        #pragma unroll
        for (int c = 0; c < 16; c++) v += s[c][tid];
        g_gate[t * NHEADS + tid] = 1.0f / (1.0f + expf(-v));
    }
}

// ============================================================
// 4) RoPE (interleaved) in-place on q and k planes
// ============================================================
__global__ __launch_bounds__(256) void rope_k(const float* __restrict__ freqs)
{
    int t = blockIdx.x;
    int pos = t & (SEQ - 1);
    for (int p = threadIdx.x; p < 1024; p += 256) {
        int mat = p >> 9;
        int rem = p & 511;
        int h = rem >> 5;
        int i = rem & 31;
        float f = (float)pos * freqs[i];
        float sn, cs;
        sincosf(f, &sn, &cs);
        float2* ptr = (float2*)(g_qkv + (size_t)t * QKVC + mat * 1024 + h * DH + 2 * i);
        float2 v = *ptr;
        *ptr = make_float2(v.x * cs - v.y * sn, v.y * cs + v.x * sn);
    }
}

// ============================================================
// 5) Flash attention on tf32 tensor cores + gate in epilogue.
//    grid (SEQ/64, NHEADS, BATCH), 128 thr = 4 warps.
//    Warp owns 16 q-rows x all 64 keys -> no cross-warp softmax.
//    P (C-frag) -> A-frag via shfl permutation, no smem round trip.
// ============================================================
#define AQP 76   // Q/K row pad: (12g+tig) mod 32 distinct
#define AVP 72   // V row pad:   (8tig+g) mod 32 distinct
#define ATTN_SMEM ((2*64*AQP + 64*AVP)*4)
__global__ __launch_bounds__(128) void attn_k()
{
    extern __shared__ float sm[];
    float* Qs = sm;                    // [64][76]
    float* Ks = sm + 64*AQP;           // [64][76]
    float* Vs = sm + 2*64*AQP;         // [64][72]

    int qt = blockIdx.x, h = blockIdx.y, b = blockIdx.z;
    int tid = threadIdx.x, warp = tid >> 5, lane = tid & 31;
    int g = lane >> 2, tig = lane & 3;
    int tBase = b * SEQ + qt * 64;
    int r0 = warp * 16;
    const float scale = 0.125f;

    // load Q tile (scaled + tf32)
    for (int idx = tid; idx < 64 * 16; idx += 128) {
        int r = idx >> 4, c4 = (idx & 15) << 2;
        float4 v = *(const float4*)(g_qkv + (size_t)(tBase + r) * QKVC + h * DH + c4);
        *(float4*)&Qs[r * AQP + c4] = make_float4(tf32r(v.x*scale), tf32r(v.y*scale),
                                                  tf32r(v.z*scale), tf32r(v.w*scale));
    }

    float mrow0 = -INFINITY, mrow1 = -INFINITY, lrow0 = 0.0f, lrow1 = 0.0f;
    float o[8][4];
    #pragma unroll
    for (int nt = 0; nt < 8; nt++)
        #pragma unroll
        for (int r = 0; r < 4; r++) o[nt][r] = 0.0f;

    int srcA = (lane & ~3) | (tig >> 1);
    int srcB = srcA + 2;
    bool codd = (tig & 1);

    for (int kt = 0; kt < SEQ / 64; kt++) {
        __syncthreads();
        int kBase = b * SEQ + kt * 64;
        for (int idx = tid; idx < 64 * 16; idx += 128) {
            int r = idx >> 4, c4 = (idx & 15) << 2;
            float4 kv = *(const float4*)(g_qkv + (size_t)(kBase + r) * QKVC + 1024 + h * DH + c4);
            *(float4*)&Ks[r * AQP + c4] = make_float4(tf32r(kv.x), tf32r(kv.y), tf32r(kv.z), tf32r(kv.w));
            float4 vv = *(const float4*)(g_qkv + (size_t)(kBase + r) * QKVC + 2048 + h * DH + c4);
            *(float4*)&Vs[r * AVP + c4] = make_float4(tf32r(vv.x), tf32r(vv.y), tf32r(vv.z), tf32r(vv.w));
        }
        __syncthreads();

        // ---- S = Q K^T : warp rows [r0, r0+16), keys 0..63 ----
        float s[8][4];
        #pragma unroll
        for (int nt = 0; nt < 8; nt++)
            #pragma unroll
            for (int r = 0; r < 4; r++) s[nt][r] = 0.0f;

        #pragma unroll
        for (int k8 = 0; k8 < 8; k8++) {
            int k0 = k8 * 8;
            unsigned a[4];
            a[0] = f2u(Qs[(r0 + g    ) * AQP + k0 + tig]);
            a[1] = f2u(Qs[(r0 + g + 8) * AQP + k0 + tig]);
            a[2] = f2u(Qs[(r0 + g    ) * AQP + k0 + tig + 4]);
            a[3] = f2u(Qs[(r0 + g + 8) * AQP + k0 + tig + 4]);
            #pragma unroll
            for (int nt = 0; nt < 8; nt++) {
                unsigned b0 = f2u(Ks[(nt * 8 + g) * AQP + k0 + tig]);
                unsigned b1 = f2u(Ks[(nt * 8 + g) * AQP + k0 + tig + 4]);
                mma_tf32(s[nt], a, b0, b1);
            }
        }

        // ---- online softmax (rows g and g+8; stats replicated over tig group) ----
        float mx0 = -INFINITY, mx1 = -INFINITY;
        #pragma unroll
        for (int nt = 0; nt < 8; nt++) {
            mx0 = fmaxf(mx0, fmaxf(s[nt][0], s[nt][1]));
            mx1 = fmaxf(mx1, fmaxf(s[nt][2], s[nt][3]));
        }
        mx0 = fmaxf(mx0, __shfl_xor_sync(0xFFFFFFFFu, mx0, 1));
        mx0 = fmaxf(mx0, __shfl_xor_sync(0xFFFFFFFFu, mx0, 2));
        mx1 = fmaxf(mx1, __shfl_xor_sync(0xFFFFFFFFu, mx1, 1));
        mx1 = fmaxf(mx1, __shfl_xor_sync(0xFFFFFFFFu, mx1, 2));

        float mn0 = fmaxf(mrow0, mx0), mn1 = fmaxf(mrow1, mx1);
        float corr0 = __expf(mrow0 - mn0), corr1 = __expf(mrow1 - mn1);
        float rs0 = 0.0f, rs1 = 0.0f;
        #pragma unroll
        for (int nt = 0; nt < 8; nt++) {
            s[nt][0] = __expf(s[nt][0] - mn0);
            s[nt][1] = __expf(s[nt][1] - mn0);
            s[nt][2] = __expf(s[nt][2] - mn1);
            s[nt][3] = __expf(s[nt][3] - mn1);
            rs0 += s[nt][0] + s[nt][1];
            rs1 += s[nt][2] + s[nt][3];
        }
        rs0 += __shfl_xor_sync(0xFFFFFFFFu, rs0, 1);
        rs0 += __shfl_xor_sync(0xFFFFFFFFu, rs0, 2);
        rs1 += __shfl_xor_sync(0xFFFFFFFFu, rs1, 1);
        rs1 += __shfl_xor_sync(0xFFFFFFFFu, rs1, 2);
        lrow0 = lrow0 * corr0 + rs0;  mrow0 = mn0;
        lrow1 = lrow1 * corr1 + rs1;  mrow1 = mn1;
        #pragma unroll
        for (int nt = 0; nt < 8; nt++) {
            o[nt][0] *= corr0; o[nt][1] *= corr0;
            o[nt][2] *= corr1; o[nt][3] *= corr1;
        }

        // ---- O += P V : C-frag -> A-frag via shfl permutation ----
        #pragma unroll
        for (int kv = 0; kv < 8; kv++) {
            float e0 = __shfl_sync(0xFFFFFFFFu, s[kv][0], srcA);
            float e1 = __shfl_sync(0xFFFFFFFFu, s[kv][1], srcA);
            float e2 = __shfl_sync(0xFFFFFFFFu, s[kv][2], srcA);
            float e3 = __shfl_sync(0xFFFFFFFFu, s[kv][3], srcA);
            float f0 = __shfl_sync(0xFFFFFFFFu, s[kv][0], srcB);
            float f1 = __shfl_sync(0xFFFFFFFFu, s[kv][1], srcB);
            float f2 = __shfl_sync(0xFFFFFFFFu, s[kv][2], srcB);
            float f3 = __shfl_sync(0xFFFFFFFFu, s[kv][3], srcB);
            unsigned pa[4];
            pa[0] = f2u(tf32r(codd ? e1 : e0));
            pa[1] = f2u(tf32r(codd ? e3 : e2));
            pa[2] = f2u(tf32r(codd ? f1 : f0));
            pa[3] = f2u(tf32r(codd ? f3 : f2));
            #pragma unroll
            for (int nt = 0; nt < 8; nt++) {
                unsigned b0 = f2u(Vs[(kv * 8 + tig    ) * AVP + nt * 8 + g]);
                unsigned b1 = f2u(Vs[(kv * 8 + tig + 4) * AVP + nt * 8 + g]);
                mma_tf32(o[nt], pa, b0, b1);
            }
        }
    }

    // ---- epilogue: normalize, gate, merged-head store ----
    int row0 = tBase + r0 + g;
    float sc0 = (1.0f / lrow0) * g_gate[row0 * NHEADS + h];
    float sc1 = (1.0f / lrow1) * g_gate[(row0 + 8) * NHEADS + h];
    #pragma unroll
    for (int nt = 0; nt < 8; nt++) {
        int col = h * DH + nt * 8 + 2 * tig;
        *(float2*)&g_att[(size_t)row0 * DIM + col] =
            make_float2(o[nt][0] * sc0, o[nt][1] * sc0);
        *(float2*)&g_att[(size_t)(row0 + 8) * DIM + col] =
            make_float2(o[nt][2] * sc1, o[nt][3] * sc1);
    }
}

// ============================================================
// launcher
// ============================================================
extern "C" void kernel_launch(void* const* d_in, const int* in_sizes, int n_in,
                              void* d_out, int out_size)
{
    const float* x       = (const float*)d_in[0];
    const float* gamma   = (const float*)d_in[1];
    const float* w_qkv   = (const float*)d_in[2];
    const float* w_gates = (const float*)d_in[3];
    const float* b_gates = (const float*)d_in[4];
    const float* w_out   = (const float*)d_in[5];
    const float* freqs   = (const float*)d_in[6];
    float* out = (float*)d_out;

    float *xn_p, *qkv_p, *att_p;
    cudaGetSymbolAddress((void**)&xn_p,  g_xn);
    cudaGetSymbolAddress((void**)&qkv_p, g_qkv);
    cudaGetSymbolAddress((void**)&att_p, g_att);

    cudaFuncSetAttribute(attn_k, cudaFuncAttributeMaxDynamicSharedMemorySize, ATTN_SMEM);

    rmsnorm_k<<<NTOK, 256>>>(x, gamma);
    tgemm_k<<<dim3(QKVC / 128, NTOK / 128), 256>>>(xn_p, w_qkv, qkv_p, NTOK, QKVC, DIM);
    gates_k<<<NTOK, 256>>>(w_gates, b_gates);
    rope_k<<<NTOK, 256>>>(freqs);
    attn_k<<<dim3(SEQ / 64, NHEADS, BATCH), 128, ATTN_SMEM>>>();
    tgemm_k<<<dim3(DIM / 128, NTOK / 128), 256>>>(att_p, w_out, out, NTOK, DIM, DIM);
}